// round 6
// baseline (speedup 1.0000x reference)
#include <cuda_runtime.h>
#include <cstdint>

#define T_TOK 8192
#define H_DIM 2048
#define I_DIM 4096
#define E_NUM 8
#define SWIGLU_ALPHA 1.702f
#define SWIGLU_LIMIT 7.0f

// Scratch: tf32-pre-rounded operands + activated intermediate
__device__ float g_x[(size_t)T_TOK * H_DIM];
__device__ float g_act[(size_t)T_TOK * I_DIM];
__device__ float g_wg[(size_t)E_NUM * H_DIM * I_DIM];
__device__ float g_wu[(size_t)E_NUM * H_DIM * I_DIM];
__device__ float g_wd[(size_t)E_NUM * I_DIM * H_DIM];

// ---------------------------------------------------------------------------
// Helpers
// ---------------------------------------------------------------------------
__device__ __forceinline__ uint32_t smem_u32(const void* p) {
    uint32_t a;
    asm("{ .reg .u64 t; cvta.to.shared.u64 t, %1; cvt.u32.u64 %0, t; }" : "=r"(a) : "l"(p));
    return a;
}
__device__ __forceinline__ float tf32r(float v) {
    float r;
    asm("cvt.rna.tf32.f32 %0, %1;" : "=f"(r) : "f"(v));
    return r;
}
// Operands pre-rounded to tf32 -> raw fp32 bits are exact tf32
__device__ __forceinline__ void mma8(float c[4],
                                     uint32_t a0, uint32_t a1, uint32_t a2, uint32_t a3,
                                     uint32_t b0, uint32_t b1) {
    asm("mma.sync.aligned.m16n8k8.row.col.f32.tf32.tf32.f32 "
        "{%0,%1,%2,%3}, {%4,%5,%6,%7}, {%8,%9}, {%0,%1,%2,%3};"
        : "+f"(c[0]), "+f"(c[1]), "+f"(c[2]), "+f"(c[3])
        : "r"(a0), "r"(a1), "r"(a2), "r"(a3), "r"(b0), "r"(b1));
}
#define CP16(dst, src) \
    asm volatile("cp.async.cg.shared.global [%0], [%1], 16;" :: "r"(dst), "l"(src))
#define CP_COMMIT() asm volatile("cp.async.commit_group;")
#define CP_WAIT1()  asm volatile("cp.async.wait_group 1;")

__device__ __forceinline__ float swiglu(float g, float u) {
    g = fminf(g, SWIGLU_LIMIT);
    u = fminf(fmaxf(u, -SWIGLU_LIMIT), SWIGLU_LIMIT);
    float sig = 1.0f / (1.0f + __expf(-SWIGLU_ALPHA * g));
    return (u + 1.0f) * g * sig;
}
__device__ __forceinline__ uint32_t ldsf(const float* p) {
    return __float_as_uint(*p);
}

constexpr int APAD = 36;    // fragment bank = (4*gid + tig) % 32 -> conflict-free
constexpr int ABYTES = 128 * APAD * 4;         // 18432

// ===========================================================================
// Staging: RN-round to tf32
// ===========================================================================
__global__ __launch_bounds__(256) void round_kernel(const float4* __restrict__ in,
                                                    float4* __restrict__ out, int n4) {
    int i = blockIdx.x * 256 + threadIdx.x;
    if (i >= n4) return;
    float4 v = in[i];
    v.x = tf32r(v.x); v.y = tf32r(v.y); v.z = tf32r(v.z); v.w = tf32r(v.w);
    out[i] = v;
}

// ===========================================================================
// Fused gate+up GEMM + bias + swiglu -> g_act (tf32-rounded)
// CTA 128x128 (g+u), 512 thr, 16 warps 4x4, warp tile 32x32 per matrix
// ===========================================================================
constexpr int BPAD12 = 136;
constexpr int BBYTES12 = 32 * BPAD12 * 4;      // 17408
constexpr int STG12 = 3;
constexpr int STAGE12 = ABYTES + 2 * BBYTES12; // 53248
constexpr int DYN12 = STG12 * STAGE12;         // 159744

__global__ __launch_bounds__(512, 1)
void gemm12(const float* __restrict__ x,
            const float* __restrict__ gw,
            const float* __restrict__ uw,
            const float* __restrict__ gb,
            const float* __restrict__ ub,
            const int* __restrict__ offs,
            float* __restrict__ act)
{
    extern __shared__ float sm[];
    const uint32_t sbase = smem_u32(sm);
    const int tid = threadIdx.x, lane = tid & 31, warp = tid >> 5;
    const int wm = warp >> 2, wn = warp & 3;        // 4 x 4 warps
    const int gid = lane >> 2, tig = lane & 3;
    const int n0 = blockIdx.x * 128, m0 = blockIdx.y * 128;

    int e = 0;
#pragma unroll
    for (int i = 0; i < E_NUM - 1; i++)
        if (m0 >= offs[i]) e = i + 1;

    const float* xa  = x + (size_t)m0 * H_DIM;
    const float* gwa = gw + (size_t)e * H_DIM * I_DIM + n0;
    const float* uwa = uw + (size_t)e * H_DIM * I_DIM + n0;

    auto issue = [&](int it, int s) {
        const uint32_t sa = sbase + s * STAGE12;
        const int k0 = it * 32;
#pragma unroll
        for (int j = 0; j < 2; j++) {                 // A: 1024 chunks / 512 thr
            int idx = tid + 512 * j;
            int r = idx >> 3, c4 = idx & 7;
            CP16(sa + (uint32_t)(r * APAD + c4 * 4) * 4,
                 xa + (size_t)r * H_DIM + k0 + c4 * 4);
        }
        const uint32_t sg = sa + ABYTES, su = sa + ABYTES + BBYTES12;
#pragma unroll
        for (int j = 0; j < 2; j++) {                 // each B: 1024 chunks
            int idx = tid + 512 * j;
            int r = idx >> 5, c4 = idx & 31;
            uint32_t off = (uint32_t)(r * BPAD12 + c4 * 4) * 4;
            CP16(sg + off, gwa + (size_t)(k0 + r) * I_DIM + c4 * 4);
            CP16(su + off, uwa + (size_t)(k0 + r) * I_DIM + c4 * 4);
        }
        CP_COMMIT();
    };

    float cg[2][4][4] = {}, cu[2][4][4] = {};

    issue(0, 0);
    issue(1, 1);

    const int NIT = H_DIM / 32;   // 64
    for (int it = 0; it < NIT; ++it) {
        const int s = it % STG12;
        CP_WAIT1();
        __syncthreads();

        const float* A  = sm + s * (STAGE12 / 4);
        const float* Bg = A + ABYTES / 4;
        const float* Bu = Bg + BBYTES12 / 4;

#pragma unroll
        for (int ks = 0; ks < 4; ++ks) {
            uint32_t a[2][4];
#pragma unroll
            for (int mf = 0; mf < 2; mf++) {
                const float* ap = A + (wm * 32 + mf * 16 + gid) * APAD + ks * 8 + tig;
                a[mf][0] = ldsf(ap);
                a[mf][1] = ldsf(ap + 8 * APAD);
                a[mf][2] = ldsf(ap + 4);
                a[mf][3] = ldsf(ap + 8 * APAD + 4);
            }
#pragma unroll
            for (int nf = 0; nf < 4; nf++) {
                const int c = wn * 32 + nf * 8 + gid;
                const float* bp = Bg + (ks * 8 + tig) * BPAD12 + c;
                uint32_t b0 = ldsf(bp), b1 = ldsf(bp + 4 * BPAD12);
                const float* up = Bu + (ks * 8 + tig) * BPAD12 + c;
                uint32_t u0 = ldsf(up), u1 = ldsf(up + 4 * BPAD12);
#pragma unroll
                for (int mf = 0; mf < 2; mf++) {
                    mma8(cg[mf][nf], a[mf][0], a[mf][1], a[mf][2], a[mf][3], b0, b1);
                    mma8(cu[mf][nf], a[mf][0], a[mf][1], a[mf][2], a[mf][3], u0, u1);
                }
            }
        }
        if (it + 2 < NIT) issue(it + 2, (it + 2) % STG12);
        else CP_COMMIT();
    }

    // Epilogue: bias + swiglu -> act (tf32-rounded so gemm3 skips cvt)
#pragma unroll
    for (int nf = 0; nf < 4; nf++) {
        const int c0 = n0 + wn * 32 + nf * 8 + 2 * tig;
        const float2 gbv = *reinterpret_cast<const float2*>(gb + (size_t)e * I_DIM + c0);
        const float2 ubv = *reinterpret_cast<const float2*>(ub + (size_t)e * I_DIM + c0);
#pragma unroll
        for (int mf = 0; mf < 2; mf++) {
            const int r0 = m0 + wm * 32 + mf * 16 + gid;
            float2 o0, o1;
            o0.x = tf32r(swiglu(cg[mf][nf][0] + gbv.x, cu[mf][nf][0] + ubv.x));
            o0.y = tf32r(swiglu(cg[mf][nf][1] + gbv.y, cu[mf][nf][1] + ubv.y));
            o1.x = tf32r(swiglu(cg[mf][nf][2] + gbv.x, cu[mf][nf][2] + ubv.x));
            o1.y = tf32r(swiglu(cg[mf][nf][3] + gbv.y, cu[mf][nf][3] + ubv.y));
            *reinterpret_cast<float2*>(act + (size_t)r0 * I_DIM + c0) = o0;
            *reinterpret_cast<float2*>(act + (size_t)(r0 + 8) * I_DIM + c0) = o1;
        }
    }
}

// ===========================================================================
// Down GEMM + bias -> out. CTA 128x256, 512 thr, 16 warps 4x4, warp 32x64
// ===========================================================================
constexpr int BPAD3 = 264;
constexpr int BBYTES3 = 32 * BPAD3 * 4;        // 33792
constexpr int STG3 = 3;
constexpr int STAGE3 = ABYTES + BBYTES3;       // 52224
constexpr int DYN3 = STG3 * STAGE3;            // 156672

__global__ __launch_bounds__(512, 1)
void gemm3(const float* __restrict__ act,
           const float* __restrict__ dw,
           const float* __restrict__ db,
           const int* __restrict__ offs,
           float* __restrict__ out)
{
    extern __shared__ float sm[];
    const uint32_t sbase = smem_u32(sm);
    const int tid = threadIdx.x, lane = tid & 31, warp = tid >> 5;
    const int wm = warp >> 2, wn = warp & 3;
    const int gid = lane >> 2, tig = lane & 3;
    const int n0 = blockIdx.x * 256, m0 = blockIdx.y * 128;

    int e = 0;
#pragma unroll
    for (int i = 0; i < E_NUM - 1; i++)
        if (m0 >= offs[i]) e = i + 1;

    const float* aa  = act + (size_t)m0 * I_DIM;
    const float* dwa = dw + (size_t)e * I_DIM * H_DIM + n0;

    auto issue = [&](int it, int s) {
        const uint32_t sa = sbase + s * STAGE3;
        const int k0 = it * 32;
#pragma unroll
        for (int j = 0; j < 2; j++) {                 // A: 1024 chunks
            int idx = tid + 512 * j;
            int r = idx >> 3, c4 = idx & 7;
            CP16(sa + (uint32_t)(r * APAD + c4 * 4) * 4,
                 aa + (size_t)r * I_DIM + k0 + c4 * 4);
        }
        const uint32_t sb = sa + ABYTES;
#pragma unroll
        for (int j = 0; j < 4; j++) {                 // B: 2048 chunks
            int idx = tid + 512 * j;
            int r = idx >> 6, c4 = idx & 63;
            CP16(sb + (uint32_t)(r * BPAD3 + c4 * 4) * 4,
                 dwa + (size_t)(k0 + r) * H_DIM + c4 * 4);
        }
        CP_COMMIT();
    };

    float cc[2][8][4] = {};

    issue(0, 0);
    issue(1, 1);

    const int NIT = I_DIM / 32;   // 128
    for (int it = 0; it < NIT; ++it) {
        const int s = it % STG3;
        CP_WAIT1();
        __syncthreads();

        const float* A = sm + s * (STAGE3 / 4);
        const float* B = A + ABYTES / 4;

#pragma unroll
        for (int ks = 0; ks < 4; ++ks) {
            uint32_t a[2][4];
#pragma unroll
            for (int mf = 0; mf < 2; mf++) {
                const float* ap = A + (wm * 32 + mf * 16 + gid) * APAD + ks * 8 + tig;
                a[mf][0] = ldsf(ap);
                a[mf][1] = ldsf(ap + 8 * APAD);
                a[mf][2] = ldsf(ap + 4);
                a[mf][3] = ldsf(ap + 8 * APAD + 4);
            }
#pragma unroll
            for (int nf = 0; nf < 8; nf++) {
                const int c = wn * 64 + nf * 8 + gid;
                const float* bp = B + (ks * 8 + tig) * BPAD3 + c;
                uint32_t b0 = ldsf(bp), b1 = ldsf(bp + 4 * BPAD3);
#pragma unroll
                for (int mf = 0; mf < 2; mf++)
                    mma8(cc[mf][nf], a[mf][0], a[mf][1], a[mf][2], a[mf][3], b0, b1);
            }
        }
        if (it + 2 < NIT) issue(it + 2, (it + 2) % STG3);
        else CP_COMMIT();
    }

    // Epilogue: + down_b -> out
#pragma unroll
    for (int nf = 0; nf < 8; nf++) {
        const int c0 = n0 + wn * 64 + nf * 8 + 2 * tig;
        const float2 bv = *reinterpret_cast<const float2*>(db + (size_t)e * H_DIM + c0);
#pragma unroll
        for (int mf = 0; mf < 2; mf++) {
            const int r0 = m0 + wm * 32 + mf * 16 + gid;
            float2 o0, o1;
            o0.x = cc[mf][nf][0] + bv.x;
            o0.y = cc[mf][nf][1] + bv.y;
            o1.x = cc[mf][nf][2] + bv.x;
            o1.y = cc[mf][nf][3] + bv.y;
            *reinterpret_cast<float2*>(out + (size_t)r0 * H_DIM + c0) = o0;
            *reinterpret_cast<float2*>(out + (size_t)(r0 + 8) * H_DIM + c0) = o1;
        }
    }
}

// ===========================================================================
// Launch
// ===========================================================================
extern "C" void kernel_launch(void* const* d_in, const int* in_sizes, int n_in,
                              void* d_out, int out_size)
{
    const float* x      = (const float*)d_in[0];
    const int*   offs   = (const int*)d_in[1];
    const float* gate_w = (const float*)d_in[2];
    const float* up_w   = (const float*)d_in[3];
    const float* down_w = (const float*)d_in[4];
    const float* gate_b = (const float*)d_in[5];
    const float* up_b   = (const float*)d_in[6];
    const float* down_b = (const float*)d_in[7];
    float* out = (float*)d_out;

    float *px, *pact, *pwg, *pwu, *pwd;
    cudaGetSymbolAddress((void**)&px,   g_x);
    cudaGetSymbolAddress((void**)&pact, g_act);
    cudaGetSymbolAddress((void**)&pwg,  g_wg);
    cudaGetSymbolAddress((void**)&pwu,  g_wu);
    cudaGetSymbolAddress((void**)&pwd,  g_wd);

    cudaFuncSetAttribute(gemm12, cudaFuncAttributeMaxDynamicSharedMemorySize, DYN12);
    cudaFuncSetAttribute(gemm3,  cudaFuncAttributeMaxDynamicSharedMemorySize, DYN3);

    // Staging: RN-round operands to tf32
    {
        int n4 = T_TOK * H_DIM / 4;
        round_kernel<<<(n4 + 255) / 256, 256>>>((const float4*)x, (float4*)px, n4);
    }
    {
        int n4 = E_NUM * H_DIM * I_DIM / 4;
        round_kernel<<<(n4 + 255) / 256, 256>>>((const float4*)gate_w, (float4*)pwg, n4);
        round_kernel<<<(n4 + 255) / 256, 256>>>((const float4*)up_w,   (float4*)pwu, n4);
        round_kernel<<<(n4 + 255) / 256, 256>>>((const float4*)down_w, (float4*)pwd, n4);
    }
    {
        dim3 grid(I_DIM / 128, T_TOK / 128);   // 32 x 64
        gemm12<<<grid, 512, DYN12>>>(px, pwg, pwu, gate_b, up_b, offs, pact);
    }
    {
        dim3 grid(H_DIM / 256, T_TOK / 128);   // 8 x 64
        gemm3<<<grid, 512, DYN3>>>(pact, pwd, down_b, offs, out);
    }
}

// round 7
// speedup vs baseline: 1.8073x; 1.8073x over previous
#include <cuda_runtime.h>
#include <cuda_fp16.h>
#include <cstdint>

#define T_TOK 8192
#define H_DIM 2048
#define I_DIM 4096
#define E_NUM 8
#define SWIGLU_ALPHA 1.702f
#define SWIGLU_LIMIT 7.0f

// fp16-staged operands + fp16 activated intermediate
__device__ __half g_xh[(size_t)T_TOK * H_DIM];
__device__ __half g_acth[(size_t)T_TOK * I_DIM];
__device__ __half g_wgh[(size_t)E_NUM * H_DIM * I_DIM];
__device__ __half g_wuh[(size_t)E_NUM * H_DIM * I_DIM];
__device__ __half g_wdh[(size_t)E_NUM * I_DIM * H_DIM];

// ---------------------------------------------------------------------------
// Helpers
// ---------------------------------------------------------------------------
__device__ __forceinline__ uint32_t smem_u32(const void* p) {
    uint32_t a;
    asm("{ .reg .u64 t; cvta.to.shared.u64 t, %1; cvt.u32.u64 %0, t; }" : "=r"(a) : "l"(p));
    return a;
}
__device__ __forceinline__ void mma16(float c[4],
                                      uint32_t a0, uint32_t a1, uint32_t a2, uint32_t a3,
                                      uint32_t b0, uint32_t b1) {
    asm("mma.sync.aligned.m16n8k16.row.col.f32.f16.f16.f32 "
        "{%0,%1,%2,%3}, {%4,%5,%6,%7}, {%8,%9}, {%0,%1,%2,%3};"
        : "+f"(c[0]), "+f"(c[1]), "+f"(c[2]), "+f"(c[3])
        : "r"(a0), "r"(a1), "r"(a2), "r"(a3), "r"(b0), "r"(b1));
}
#define LDMX4(r0, r1, r2, r3, addr) \
    asm volatile("ldmatrix.sync.aligned.m8n8.x4.shared.b16 {%0,%1,%2,%3}, [%4];" \
        : "=r"(r0), "=r"(r1), "=r"(r2), "=r"(r3) : "r"(addr))
#define LDMX4T(r0, r1, r2, r3, addr) \
    asm volatile("ldmatrix.sync.aligned.m8n8.x4.trans.shared.b16 {%0,%1,%2,%3}, [%4];" \
        : "=r"(r0), "=r"(r1), "=r"(r2), "=r"(r3) : "r"(addr))
#define CP16(dst, src) \
    asm volatile("cp.async.cg.shared.global [%0], [%1], 16;" :: "r"(dst), "l"(src))
#define CP_COMMIT() asm volatile("cp.async.commit_group;")
#define CP_WAIT2()  asm volatile("cp.async.wait_group 2;")

__device__ __forceinline__ float swiglu(float g, float u) {
    g = fminf(g, SWIGLU_LIMIT);
    u = fminf(fmaxf(u, -SWIGLU_LIMIT), SWIGLU_LIMIT);
    float sig = 1.0f / (1.0f + __expf(-SWIGLU_ALPHA * g));
    return (u + 1.0f) * g * sig;
}

constexpr int APADH = 40;                     // halves; 80B row stride -> conflict-free ldmatrix
constexpr int ABYTES = 128 * APADH * 2;       // 10240

// ===========================================================================
// Staging: fp32 -> fp16 (RN)
// ===========================================================================
__global__ __launch_bounds__(256) void to_half_kernel(const float4* __restrict__ in,
                                                      __half2* __restrict__ out, int n4) {
    int i = blockIdx.x * 256 + threadIdx.x;
    if (i >= n4) return;
    float4 v = in[i];
    out[2 * i]     = __floats2half2_rn(v.x, v.y);
    out[2 * i + 1] = __floats2half2_rn(v.z, v.w);
}

// ===========================================================================
// Fused gate+up GEMM + bias + swiglu -> g_acth (fp16)
// CTA 128x128 (both g,u), 256 thr, 8 warps 2x4, warp tile 64x32 per matrix
// ===========================================================================
constexpr int BPADH12 = 136;                       // halves
constexpr int BBYTES12 = 32 * BPADH12 * 2;         // 8704
constexpr int STG12 = 4;
constexpr int STAGE12 = ABYTES + 2 * BBYTES12;     // 27648
constexpr int DYN12 = STG12 * STAGE12;             // 110592

__global__ __launch_bounds__(256, 1)
void gemm12(const __half* __restrict__ x,
            const __half* __restrict__ gw,
            const __half* __restrict__ uw,
            const float* __restrict__ gb,
            const float* __restrict__ ub,
            const int* __restrict__ offs,
            __half* __restrict__ act)
{
    extern __shared__ __align__(16) char smraw[];
    const uint32_t sbase = smem_u32(smraw);
    const int tid = threadIdx.x, lane = tid & 31, warp = tid >> 5;
    const int wm = warp >> 2, wn = warp & 3;    // 2 x 4
    const int gid = lane >> 2, tig = lane & 3;
    const int n0 = blockIdx.x * 128, m0 = blockIdx.y * 128;

    int e = 0;
#pragma unroll
    for (int i = 0; i < E_NUM - 1; i++)
        if (m0 >= offs[i]) e = i + 1;

    const __half* xa  = x + (size_t)m0 * H_DIM;
    const __half* gwa = gw + (size_t)e * H_DIM * I_DIM + n0;
    const __half* uwa = uw + (size_t)e * H_DIM * I_DIM + n0;

    auto issue = [&](int it, int s) {
        const uint32_t sa = sbase + s * STAGE12;
        const int k0 = it * 32;
#pragma unroll
        for (int j = 0; j < 2; j++) {               // A: 128r x 4 chunks = 512
            int idx = tid + 256 * j;
            int r = idx >> 2, c8 = idx & 3;
            CP16(sa + (uint32_t)(r * APADH + c8 * 8) * 2,
                 xa + (size_t)r * H_DIM + k0 + c8 * 8);
        }
        const uint32_t sg = sa + ABYTES, su = sg + BBYTES12;
#pragma unroll
        for (int j = 0; j < 2; j++) {               // each B: 32r x 16 chunks = 512
            int idx = tid + 256 * j;
            int r = idx >> 4, c8 = idx & 15;
            uint32_t off = (uint32_t)(r * BPADH12 + c8 * 8) * 2;
            CP16(sg + off, gwa + (size_t)(k0 + r) * I_DIM + c8 * 8);
            CP16(su + off, uwa + (size_t)(k0 + r) * I_DIM + c8 * 8);
        }
        CP_COMMIT();
    };

    float cg[4][4][4] = {}, cu[4][4][4] = {};

    issue(0, 0); issue(1, 1); issue(2, 2);

    // per-thread ldmatrix address components
    const uint32_t aRow = wm * 64 + (lane & 15);            // + mf*16
    const uint32_t aCol = (lane >> 4) * 8;                  // + ks*16
    const uint32_t bRow = (lane & 15);                      // k within tile (+ks*16)
    const uint32_t bCol = wn * 32 + (lane >> 4) * 8;        // + nfp*16

    const int NIT = H_DIM / 32;   // 64
    for (int it = 0; it < NIT; ++it) {
        const int s = it & 3;
        CP_WAIT2();
        __syncthreads();

        const uint32_t sA = sbase + s * STAGE12;
        const uint32_t sG = sA + ABYTES;
        const uint32_t sU = sG + BBYTES12;

#pragma unroll
        for (int ks = 0; ks < 2; ++ks) {
            uint32_t a[4][4];
#pragma unroll
            for (int mf = 0; mf < 4; mf++) {
                uint32_t ad = sA + ((aRow + mf * 16) * APADH + aCol + ks * 16) * 2;
                LDMX4(a[mf][0], a[mf][1], a[mf][2], a[mf][3], ad);
            }
#pragma unroll
            for (int nfp = 0; nfp < 2; nfp++) {
                uint32_t boff = ((bRow + ks * 16) * BPADH12 + bCol + nfp * 16) * 2;
                uint32_t bg0, bg1, bg2, bg3, bu0, bu1, bu2, bu3;
                LDMX4T(bg0, bg1, bg2, bg3, sG + boff);
                LDMX4T(bu0, bu1, bu2, bu3, sU + boff);
#pragma unroll
                for (int mf = 0; mf < 4; mf++) {
                    mma16(cg[mf][2 * nfp],     a[mf][0], a[mf][1], a[mf][2], a[mf][3], bg0, bg1);
                    mma16(cg[mf][2 * nfp + 1], a[mf][0], a[mf][1], a[mf][2], a[mf][3], bg2, bg3);
                    mma16(cu[mf][2 * nfp],     a[mf][0], a[mf][1], a[mf][2], a[mf][3], bu0, bu1);
                    mma16(cu[mf][2 * nfp + 1], a[mf][0], a[mf][1], a[mf][2], a[mf][3], bu2, bu3);
                }
            }
        }
        if (it + 3 < NIT) issue(it + 3, (it + 3) & 3);
        else CP_COMMIT();
    }

    // Epilogue: bias + swiglu -> fp16 act
#pragma unroll
    for (int nf = 0; nf < 4; nf++) {
        const int c0 = n0 + wn * 32 + nf * 8 + 2 * tig;
        const float2 gbv = *reinterpret_cast<const float2*>(gb + (size_t)e * I_DIM + c0);
        const float2 ubv = *reinterpret_cast<const float2*>(ub + (size_t)e * I_DIM + c0);
#pragma unroll
        for (int mf = 0; mf < 4; mf++) {
            const int r0 = m0 + wm * 64 + mf * 16 + gid;
            float o00 = swiglu(cg[mf][nf][0] + gbv.x, cu[mf][nf][0] + ubv.x);
            float o01 = swiglu(cg[mf][nf][1] + gbv.y, cu[mf][nf][1] + ubv.y);
            float o10 = swiglu(cg[mf][nf][2] + gbv.x, cu[mf][nf][2] + ubv.x);
            float o11 = swiglu(cg[mf][nf][3] + gbv.y, cu[mf][nf][3] + ubv.y);
            *reinterpret_cast<__half2*>(act + (size_t)r0 * I_DIM + c0) = __floats2half2_rn(o00, o01);
            *reinterpret_cast<__half2*>(act + (size_t)(r0 + 8) * I_DIM + c0) = __floats2half2_rn(o10, o11);
        }
    }
}

// ===========================================================================
// Down GEMM + bias -> out (fp32). CTA 128x256, 8 warps 2x4, warp 64x64
// ===========================================================================
constexpr int BPADH3 = 264;
constexpr int BBYTES3 = 32 * BPADH3 * 2;        // 16896
constexpr int STG3 = 4;
constexpr int STAGE3 = ABYTES + BBYTES3;        // 27136
constexpr int DYN3 = STG3 * STAGE3;             // 108544

__global__ __launch_bounds__(256, 1)
void gemm3(const __half* __restrict__ act,
           const __half* __restrict__ dw,
           const float* __restrict__ db,
           const int* __restrict__ offs,
           float* __restrict__ out)
{
    extern __shared__ __align__(16) char smraw[];
    const uint32_t sbase = smem_u32(smraw);
    const int tid = threadIdx.x, lane = tid & 31, warp = tid >> 5;
    const int wm = warp >> 2, wn = warp & 3;
    const int gid = lane >> 2, tig = lane & 3;
    const int n0 = blockIdx.x * 256, m0 = blockIdx.y * 128;

    int e = 0;
#pragma unroll
    for (int i = 0; i < E_NUM - 1; i++)
        if (m0 >= offs[i]) e = i + 1;

    const __half* aa  = act + (size_t)m0 * I_DIM;
    const __half* dwa = dw + (size_t)e * I_DIM * H_DIM + n0;

    auto issue = [&](int it, int s) {
        const uint32_t sa = sbase + s * STAGE3;
        const int k0 = it * 32;
#pragma unroll
        for (int j = 0; j < 2; j++) {               // A: 512 chunks
            int idx = tid + 256 * j;
            int r = idx >> 2, c8 = idx & 3;
            CP16(sa + (uint32_t)(r * APADH + c8 * 8) * 2,
                 aa + (size_t)r * I_DIM + k0 + c8 * 8);
        }
        const uint32_t sb = sa + ABYTES;
#pragma unroll
        for (int j = 0; j < 4; j++) {               // B: 32r x 32 chunks = 1024
            int idx = tid + 256 * j;
            int r = idx >> 5, c8 = idx & 31;
            CP16(sb + (uint32_t)(r * BPADH3 + c8 * 8) * 2,
                 dwa + (size_t)(k0 + r) * H_DIM + c8 * 8);
        }
        CP_COMMIT();
    };

    float cc[4][8][4] = {};

    issue(0, 0); issue(1, 1); issue(2, 2);

    const uint32_t aRow = wm * 64 + (lane & 15);
    const uint32_t aCol = (lane >> 4) * 8;
    const uint32_t bRow = (lane & 15);
    const uint32_t bCol = wn * 64 + (lane >> 4) * 8;

    const int NIT = I_DIM / 32;   // 128
    for (int it = 0; it < NIT; ++it) {
        const int s = it & 3;
        CP_WAIT2();
        __syncthreads();

        const uint32_t sA = sbase + s * STAGE3;
        const uint32_t sB = sA + ABYTES;

#pragma unroll
        for (int ks = 0; ks < 2; ++ks) {
            uint32_t a[4][4];
#pragma unroll
            for (int mf = 0; mf < 4; mf++) {
                uint32_t ad = sA + ((aRow + mf * 16) * APADH + aCol + ks * 16) * 2;
                LDMX4(a[mf][0], a[mf][1], a[mf][2], a[mf][3], ad);
            }
#pragma unroll
            for (int nfp = 0; nfp < 4; nfp++) {
                uint32_t b0, b1, b2, b3;
                LDMX4T(b0, b1, b2, b3,
                       sB + ((bRow + ks * 16) * BPADH3 + bCol + nfp * 16) * 2);
#pragma unroll
                for (int mf = 0; mf < 4; mf++) {
                    mma16(cc[mf][2 * nfp],     a[mf][0], a[mf][1], a[mf][2], a[mf][3], b0, b1);
                    mma16(cc[mf][2 * nfp + 1], a[mf][0], a[mf][1], a[mf][2], a[mf][3], b2, b3);
                }
            }
        }
        if (it + 3 < NIT) issue(it + 3, (it + 3) & 3);
        else CP_COMMIT();
    }

    // Epilogue: + down_b -> out
#pragma unroll
    for (int nf = 0; nf < 8; nf++) {
        const int c0 = n0 + wn * 64 + nf * 8 + 2 * tig;
        const float2 bv = *reinterpret_cast<const float2*>(db + (size_t)e * H_DIM + c0);
#pragma unroll
        for (int mf = 0; mf < 4; mf++) {
            const int r0 = m0 + wm * 64 + mf * 16 + gid;
            float2 o0, o1;
            o0.x = cc[mf][nf][0] + bv.x;
            o0.y = cc[mf][nf][1] + bv.y;
            o1.x = cc[mf][nf][2] + bv.x;
            o1.y = cc[mf][nf][3] + bv.y;
            *reinterpret_cast<float2*>(out + (size_t)r0 * H_DIM + c0) = o0;
            *reinterpret_cast<float2*>(out + (size_t)(r0 + 8) * H_DIM + c0) = o1;
        }
    }
}

// ===========================================================================
// Launch
// ===========================================================================
extern "C" void kernel_launch(void* const* d_in, const int* in_sizes, int n_in,
                              void* d_out, int out_size)
{
    const float* x      = (const float*)d_in[0];
    const int*   offs   = (const int*)d_in[1];
    const float* gate_w = (const float*)d_in[2];
    const float* up_w   = (const float*)d_in[3];
    const float* down_w = (const float*)d_in[4];
    const float* gate_b = (const float*)d_in[5];
    const float* up_b   = (const float*)d_in[6];
    const float* down_b = (const float*)d_in[7];
    float* out = (float*)d_out;

    __half *pxh, *pacth, *pwgh, *pwuh, *pwdh;
    cudaGetSymbolAddress((void**)&pxh,   g_xh);
    cudaGetSymbolAddress((void**)&pacth, g_acth);
    cudaGetSymbolAddress((void**)&pwgh,  g_wgh);
    cudaGetSymbolAddress((void**)&pwuh,  g_wuh);
    cudaGetSymbolAddress((void**)&pwdh,  g_wdh);

    cudaFuncSetAttribute(gemm12, cudaFuncAttributeMaxDynamicSharedMemorySize, DYN12);
    cudaFuncSetAttribute(gemm3,  cudaFuncAttributeMaxDynamicSharedMemorySize, DYN3);

    // Staging: fp32 -> fp16
    {
        int n4 = T_TOK * H_DIM / 4;
        to_half_kernel<<<(n4 + 255) / 256, 256>>>((const float4*)x, (__half2*)pxh, n4);
    }
    {
        int n4 = E_NUM * H_DIM * I_DIM / 4;
        to_half_kernel<<<(n4 + 255) / 256, 256>>>((const float4*)gate_w, (__half2*)pwgh, n4);
        to_half_kernel<<<(n4 + 255) / 256, 256>>>((const float4*)up_w,   (__half2*)pwuh, n4);
        to_half_kernel<<<(n4 + 255) / 256, 256>>>((const float4*)down_w, (__half2*)pwdh, n4);
    }
    {
        dim3 grid(I_DIM / 128, T_TOK / 128);   // 32 x 64
        gemm12<<<grid, 256, DYN12>>>(pxh, pwgh, pwuh, gate_b, up_b, offs, pacth);
    }
    {
        dim3 grid(H_DIM / 256, T_TOK / 128);   // 8 x 64
        gemm3<<<grid, 256, DYN3>>>(pacth, pwdh, down_b, offs, out);
    }
}

// round 9
// speedup vs baseline: 1.9708x; 1.0905x over previous
#include <cuda_runtime.h>
#include <cuda_fp16.h>
#include <cstdint>

#define T_TOK 8192
#define H_DIM 2048
#define I_DIM 4096
#define E_NUM 8
#define SWIGLU_ALPHA 1.702f
#define SWIGLU_LIMIT 7.0f

// fp16-staged operands + fp16 activated intermediate
__device__ __half g_xh[(size_t)T_TOK * H_DIM];
__device__ __half g_acth[(size_t)T_TOK * I_DIM];
__device__ __half g_wgh[(size_t)E_NUM * H_DIM * I_DIM];
__device__ __half g_wuh[(size_t)E_NUM * H_DIM * I_DIM];
__device__ __half g_wdh[(size_t)E_NUM * I_DIM * H_DIM];

// ---------------------------------------------------------------------------
// Helpers
// ---------------------------------------------------------------------------
__device__ __forceinline__ uint32_t smem_u32(const void* p) {
    uint32_t a;
    asm("{ .reg .u64 t; cvta.to.shared.u64 t, %1; cvt.u32.u64 %0, t; }" : "=r"(a) : "l"(p));
    return a;
}
__device__ __forceinline__ uint32_t h2_as_u32(__half2 h) {
    return *reinterpret_cast<uint32_t*>(&h);
}
__device__ __forceinline__ void mma16(float c[4],
                                      uint32_t a0, uint32_t a1, uint32_t a2, uint32_t a3,
                                      uint32_t b0, uint32_t b1) {
    asm("mma.sync.aligned.m16n8k16.row.col.f32.f16.f16.f32 "
        "{%0,%1,%2,%3}, {%4,%5,%6,%7}, {%8,%9}, {%0,%1,%2,%3};"
        : "+f"(c[0]), "+f"(c[1]), "+f"(c[2]), "+f"(c[3])
        : "r"(a0), "r"(a1), "r"(a2), "r"(a3), "r"(b0), "r"(b1));
}
#define LDMX4(r0, r1, r2, r3, addr) \
    asm volatile("ldmatrix.sync.aligned.m8n8.x4.shared.b16 {%0,%1,%2,%3}, [%4];" \
        : "=r"(r0), "=r"(r1), "=r"(r2), "=r"(r3) : "r"(addr))
#define LDMX4T(r0, r1, r2, r3, addr) \
    asm volatile("ldmatrix.sync.aligned.m8n8.x4.trans.shared.b16 {%0,%1,%2,%3}, [%4];" \
        : "=r"(r0), "=r"(r1), "=r"(r2), "=r"(r3) : "r"(addr))
#define CP16(dst, src) \
    asm volatile("cp.async.cg.shared.global [%0], [%1], 16;" :: "r"(dst), "l"(src))
#define CP_COMMIT() asm volatile("cp.async.commit_group;")
#define CP_WAIT2()  asm volatile("cp.async.wait_group 2;")

__device__ __forceinline__ float swiglu(float g, float u) {
    g = fminf(g, SWIGLU_LIMIT);
    u = fminf(fmaxf(u, -SWIGLU_LIMIT), SWIGLU_LIMIT);
    float sig = 1.0f / (1.0f + __expf(-SWIGLU_ALPHA * g));
    return (u + 1.0f) * g * sig;
}

// BK = 64 halves per k-tile
constexpr int APADH = 72;                     // 144B row stride -> conflict-free ldmatrix
constexpr int ABYTES = 128 * APADH * 2;       // 18432

// ===========================================================================
// Staging: fp32 -> fp16 (RN), 16B stores
// ===========================================================================
__global__ __launch_bounds__(256) void to_half_kernel(const float4* __restrict__ in,
                                                      uint4* __restrict__ out, int n8) {
    int i = blockIdx.x * 256 + threadIdx.x;
    if (i >= n8) return;
    float4 v0 = in[2 * i], v1 = in[2 * i + 1];
    uint4 o;
    o.x = h2_as_u32(__floats2half2_rn(v0.x, v0.y));
    o.y = h2_as_u32(__floats2half2_rn(v0.z, v0.w));
    o.z = h2_as_u32(__floats2half2_rn(v1.x, v1.y));
    o.w = h2_as_u32(__floats2half2_rn(v1.z, v1.w));
    out[i] = o;
}

// ===========================================================================
// Fused gate+up GEMM + bias + swiglu -> g_acth (fp16)
// CTA 128x128 (both g,u), 256 thr, 8 warps 2x4, warp 64x32/matrix, BK=64
// ===========================================================================
constexpr int BPADH12 = 136;
constexpr int BBYTES12 = 64 * BPADH12 * 2;         // 17408
constexpr int STG12 = 4;
constexpr int STAGE12 = ABYTES + 2 * BBYTES12;     // 53248
constexpr int DYN12 = STG12 * STAGE12;             // 212992

__global__ __launch_bounds__(256, 1)
void gemm12(const __half* __restrict__ x,
            const __half* __restrict__ gw,
            const __half* __restrict__ uw,
            const float* __restrict__ gb,
            const float* __restrict__ ub,
            const int* __restrict__ offs,
            __half* __restrict__ act)
{
    extern __shared__ __align__(16) char smraw[];
    const uint32_t sbase = smem_u32(smraw);
    const int tid = threadIdx.x, lane = tid & 31, warp = tid >> 5;
    const int wm = warp >> 2, wn = warp & 3;
    const int gid = lane >> 2, tig = lane & 3;
    const int n0 = blockIdx.x * 128, m0 = blockIdx.y * 128;

    int e = 0;
#pragma unroll
    for (int i = 0; i < E_NUM - 1; i++)
        if (m0 >= offs[i]) e = i + 1;

    const __half* xa  = x + (size_t)m0 * H_DIM;
    const __half* gwa = gw + (size_t)e * H_DIM * I_DIM + n0;
    const __half* uwa = uw + (size_t)e * H_DIM * I_DIM + n0;

    auto issue = [&](int it, int s) {
        const uint32_t sa = sbase + s * STAGE12;
        const int k0 = it * 64;
#pragma unroll
        for (int j = 0; j < 4; j++) {               // A: 128r x 8 chunks = 1024
            int idx = tid + 256 * j;
            int r = idx >> 3, c8 = idx & 7;
            CP16(sa + (uint32_t)(r * APADH + c8 * 8) * 2,
                 xa + (size_t)r * H_DIM + k0 + c8 * 8);
        }
        const uint32_t sg = sa + ABYTES, su = sg + BBYTES12;
#pragma unroll
        for (int j = 0; j < 4; j++) {               // each B: 64r x 16 chunks = 1024
            int idx = tid + 256 * j;
            int r = idx >> 4, c8 = idx & 15;
            uint32_t off = (uint32_t)(r * BPADH12 + c8 * 8) * 2;
            CP16(sg + off, gwa + (size_t)(k0 + r) * I_DIM + c8 * 8);
            CP16(su + off, uwa + (size_t)(k0 + r) * I_DIM + c8 * 8);
        }
        CP_COMMIT();
    };

    float cg[4][4][4] = {}, cu[4][4][4] = {};

    issue(0, 0); issue(1, 1); issue(2, 2);

    const uint32_t aRow = wm * 64 + (lane & 15);
    const uint32_t aCol = (lane >> 4) * 8;
    const uint32_t bRow = (lane & 15);
    const uint32_t bCol = wn * 32 + (lane >> 4) * 8;

    const int NIT = H_DIM / 64;   // 32
#pragma unroll 1
    for (int it0 = 0; it0 < NIT; it0 += 4) {
#pragma unroll
        for (int sub = 0; sub < 4; ++sub) {
            const int it = it0 + sub;
            CP_WAIT2();
            __syncthreads();

            const uint32_t sA = sbase + sub * STAGE12;
            const uint32_t sG = sA + ABYTES;
            const uint32_t sU = sG + BBYTES12;

#pragma unroll
            for (int ks = 0; ks < 4; ++ks) {
                uint32_t a[4][4];
#pragma unroll
                for (int mf = 0; mf < 4; mf++) {
                    uint32_t ad = sA + ((aRow + mf * 16) * APADH + aCol + ks * 16) * 2;
                    LDMX4(a[mf][0], a[mf][1], a[mf][2], a[mf][3], ad);
                }
#pragma unroll
                for (int nfp = 0; nfp < 2; nfp++) {
                    uint32_t boff = ((bRow + ks * 16) * BPADH12 + bCol + nfp * 16) * 2;
                    uint32_t bg0, bg1, bg2, bg3, bu0, bu1, bu2, bu3;
                    LDMX4T(bg0, bg1, bg2, bg3, sG + boff);
                    LDMX4T(bu0, bu1, bu2, bu3, sU + boff);
#pragma unroll
                    for (int mf = 0; mf < 4; mf++) {
                        mma16(cg[mf][2 * nfp],     a[mf][0], a[mf][1], a[mf][2], a[mf][3], bg0, bg1);
                        mma16(cg[mf][2 * nfp + 1], a[mf][0], a[mf][1], a[mf][2], a[mf][3], bg2, bg3);
                        mma16(cu[mf][2 * nfp],     a[mf][0], a[mf][1], a[mf][2], a[mf][3], bu0, bu1);
                        mma16(cu[mf][2 * nfp + 1], a[mf][0], a[mf][1], a[mf][2], a[mf][3], bu2, bu3);
                    }
                }
            }
            if (it + 3 < NIT) issue(it + 3, (it + 3) & 3);
            else CP_COMMIT();
        }
    }

    // Epilogue: bias + swiglu -> fp16 act
#pragma unroll
    for (int nf = 0; nf < 4; nf++) {
        const int c0 = n0 + wn * 32 + nf * 8 + 2 * tig;
        const float2 gbv = *reinterpret_cast<const float2*>(gb + (size_t)e * I_DIM + c0);
        const float2 ubv = *reinterpret_cast<const float2*>(ub + (size_t)e * I_DIM + c0);
#pragma unroll
        for (int mf = 0; mf < 4; mf++) {
            const int r0 = m0 + wm * 64 + mf * 16 + gid;
            float o00 = swiglu(cg[mf][nf][0] + gbv.x, cu[mf][nf][0] + ubv.x);
            float o01 = swiglu(cg[mf][nf][1] + gbv.y, cu[mf][nf][1] + ubv.y);
            float o10 = swiglu(cg[mf][nf][2] + gbv.x, cu[mf][nf][2] + ubv.x);
            float o11 = swiglu(cg[mf][nf][3] + gbv.y, cu[mf][nf][3] + ubv.y);
            *reinterpret_cast<__half2*>(act + (size_t)r0 * I_DIM + c0) = __floats2half2_rn(o00, o01);
            *reinterpret_cast<__half2*>(act + (size_t)(r0 + 8) * I_DIM + c0) = __floats2half2_rn(o10, o11);
        }
    }
}

// ===========================================================================
// Down GEMM + bias -> out (fp32). CTA 128x256, 8 warps 2x4, warp 64x64, BK=64
// ===========================================================================
constexpr int BPADH3 = 264;
constexpr int BBYTES3 = 64 * BPADH3 * 2;        // 33792
constexpr int STG3 = 4;
constexpr int STAGE3 = ABYTES + BBYTES3;        // 52224
constexpr int DYN3 = STG3 * STAGE3;             // 208896

__global__ __launch_bounds__(256, 1)
void gemm3(const __half* __restrict__ act,
           const __half* __restrict__ dw,
           const float* __restrict__ db,
           const int* __restrict__ offs,
           float* __restrict__ out)
{
    extern __shared__ __align__(16) char smraw[];
    const uint32_t sbase = smem_u32(smraw);
    const int tid = threadIdx.x, lane = tid & 31, warp = tid >> 5;
    const int wm = warp >> 2, wn = warp & 3;
    const int gid = lane >> 2, tig = lane & 3;
    const int n0 = blockIdx.x * 256, m0 = blockIdx.y * 128;

    int e = 0;
#pragma unroll
    for (int i = 0; i < E_NUM - 1; i++)
        if (m0 >= offs[i]) e = i + 1;

    const __half* aa  = act + (size_t)m0 * I_DIM;
    const __half* dwa = dw + (size_t)e * I_DIM * H_DIM + n0;

    auto issue = [&](int it, int s) {
        const uint32_t sa = sbase + s * STAGE3;
        const int k0 = it * 64;
#pragma unroll
        for (int j = 0; j < 4; j++) {               // A: 1024 chunks
            int idx = tid + 256 * j;
            int r = idx >> 3, c8 = idx & 7;
            CP16(sa + (uint32_t)(r * APADH + c8 * 8) * 2,
                 aa + (size_t)r * I_DIM + k0 + c8 * 8);
        }
        const uint32_t sb = sa + ABYTES;
#pragma unroll
        for (int j = 0; j < 8; j++) {               // B: 64r x 32 chunks = 2048
            int idx = tid + 256 * j;
            int r = idx >> 5, c8 = idx & 31;
            CP16(sb + (uint32_t)(r * BPADH3 + c8 * 8) * 2,
                 dwa + (size_t)(k0 + r) * H_DIM + c8 * 8);
        }
        CP_COMMIT();
    };

    float cc[4][8][4] = {};

    issue(0, 0); issue(1, 1); issue(2, 2);

    const uint32_t aRow = wm * 64 + (lane & 15);
    const uint32_t aCol = (lane >> 4) * 8;
    const uint32_t bRow = (lane & 15);
    const uint32_t bCol = wn * 64 + (lane >> 4) * 8;

    const int NIT = I_DIM / 64;   // 64
#pragma unroll 1
    for (int it0 = 0; it0 < NIT; it0 += 4) {
#pragma unroll
        for (int sub = 0; sub < 4; ++sub) {
            const int it = it0 + sub;
            CP_WAIT2();
            __syncthreads();

            const uint32_t sA = sbase + sub * STAGE3;
            const uint32_t sB = sA + ABYTES;

#pragma unroll
            for (int ks = 0; ks < 4; ++ks) {
                uint32_t a[4][4];
#pragma unroll
                for (int mf = 0; mf < 4; mf++) {
                    uint32_t ad = sA + ((aRow + mf * 16) * APADH + aCol + ks * 16) * 2;
                    LDMX4(a[mf][0], a[mf][1], a[mf][2], a[mf][3], ad);
                }
#pragma unroll
                for (int nfp = 0; nfp < 4; nfp++) {
                    uint32_t b0, b1, b2, b3;
                    LDMX4T(b0, b1, b2, b3,
                           sB + ((bRow + ks * 16) * BPADH3 + bCol + nfp * 16) * 2);
#pragma unroll
                    for (int mf = 0; mf < 4; mf++) {
                        mma16(cc[mf][2 * nfp],     a[mf][0], a[mf][1], a[mf][2], a[mf][3], b0, b1);
                        mma16(cc[mf][2 * nfp + 1], a[mf][0], a[mf][1], a[mf][2], a[mf][3], b2, b3);
                    }
                }
            }
            if (it + 3 < NIT) issue(it + 3, (it + 3) & 3);
            else CP_COMMIT();
        }
    }

    // Epilogue: + down_b -> out
#pragma unroll
    for (int nf = 0; nf < 8; nf++) {
        const int c0 = n0 + wn * 64 + nf * 8 + 2 * tig;
        const float2 bv = *reinterpret_cast<const float2*>(db + (size_t)e * H_DIM + c0);
#pragma unroll
        for (int mf = 0; mf < 4; mf++) {
            const int r0 = m0 + wm * 64 + mf * 16 + gid;
            float2 o0, o1;
            o0.x = cc[mf][nf][0] + bv.x;
            o0.y = cc[mf][nf][1] + bv.y;
            o1.x = cc[mf][nf][2] + bv.x;
            o1.y = cc[mf][nf][3] + bv.y;
            *reinterpret_cast<float2*>(out + (size_t)r0 * H_DIM + c0) = o0;
            *reinterpret_cast<float2*>(out + (size_t)(r0 + 8) * H_DIM + c0) = o1;
        }
    }
}

// ===========================================================================
// Launch
// ===========================================================================
extern "C" void kernel_launch(void* const* d_in, const int* in_sizes, int n_in,
                              void* d_out, int out_size)
{
    const float* x      = (const float*)d_in[0];
    const int*   offs   = (const int*)d_in[1];
    const float* gate_w = (const float*)d_in[2];
    const float* up_w   = (const float*)d_in[3];
    const float* down_w = (const float*)d_in[4];
    const float* gate_b = (const float*)d_in[5];
    const float* up_b   = (const float*)d_in[6];
    const float* down_b = (const float*)d_in[7];
    float* out = (float*)d_out;

    __half *pxh, *pacth, *pwgh, *pwuh, *pwdh;
    cudaGetSymbolAddress((void**)&pxh,   g_xh);
    cudaGetSymbolAddress((void**)&pacth, g_acth);
    cudaGetSymbolAddress((void**)&pwgh,  g_wgh);
    cudaGetSymbolAddress((void**)&pwuh,  g_wuh);
    cudaGetSymbolAddress((void**)&pwdh,  g_wdh);

    cudaFuncSetAttribute(gemm12, cudaFuncAttributeMaxDynamicSharedMemorySize, DYN12);
    cudaFuncSetAttribute(gemm3,  cudaFuncAttributeMaxDynamicSharedMemorySize, DYN3);

    // Staging: fp32 -> fp16
    {
        int n8 = T_TOK * H_DIM / 8;
        to_half_kernel<<<(n8 + 255) / 256, 256>>>((const float4*)x, (uint4*)pxh, n8);
    }
    {
        int n8 = E_NUM * H_DIM * I_DIM / 8;
        to_half_kernel<<<(n8 + 255) / 256, 256>>>((const float4*)gate_w, (uint4*)pwgh, n8);
        to_half_kernel<<<(n8 + 255) / 256, 256>>>((const float4*)up_w,   (uint4*)pwuh, n8);
        to_half_kernel<<<(n8 + 255) / 256, 256>>>((const float4*)down_w, (uint4*)pwdh, n8);
    }
    {
        dim3 grid(I_DIM / 128, T_TOK / 128);   // 32 x 64
        gemm12<<<grid, 256, DYN12>>>(pxh, pwgh, pwuh, gate_b, up_b, offs, pacth);
    }
    {
        dim3 grid(H_DIM / 256, T_TOK / 128);   // 8 x 64
        gemm3<<<grid, 256, DYN3>>>(pacth, pwdh, down_b, offs, out);
    }
}